// round 4
// baseline (speedup 1.0000x reference)
#include <cuda_runtime.h>
#include <cstdint>

// ---------------- Problem constants ----------------
#define BATCH   8192
#define DH      1024
#define TILE_M  128             // batch rows per CTA
#define JBLK    32              // hidden cols per CTA (per gate)
#define TILE_N  128             // 4 gates * JBLK
#define KCH     32              // K elems per chunk
#define NCHUNK  64              // 2*1024 / 32
#define THREADS 256

// ---------------- SMEM layout (dynamic) ----------------
// [0,512)        bias  (4 gates x 32 floats = 512B)
// [512, ...)     2 stages of (A 16KB + B 16KB) = 65536B   (main loop)
// [512, ...)     accumulator dump 128 x 132 floats = 67584B (epilogue, aliases stages)
#define SM_BIAS     0
#define SM_STAGE    512
#define A_FLOATS    (TILE_M * KCH)     // 4096
#define STAGE_FLOATS (2 * A_FLOATS)    // A + B
#define DUMP_PITCH  132
#define SMEM_TOTAL  (512 + TILE_M * DUMP_PITCH * 4)   // 68096 >= 512 + 2*32768

__device__ __forceinline__ uint32_t f2tf32(float f) {
    uint32_t u;
    asm("cvt.rna.tf32.f32 %0, %1;" : "=r"(u) : "f"(f));
    return u;
}

__device__ __forceinline__ void mma_tf32(float* d, const uint32_t* a, const uint32_t* b) {
    asm volatile(
        "mma.sync.aligned.m16n8k8.row.col.f32.tf32.tf32.f32 "
        "{%0,%1,%2,%3}, {%4,%5,%6,%7}, {%8,%9}, {%0,%1,%2,%3};"
        : "+f"(d[0]), "+f"(d[1]), "+f"(d[2]), "+f"(d[3])
        : "r"(a[0]), "r"(a[1]), "r"(a[2]), "r"(a[3]), "r"(b[0]), "r"(b[1]));
}

__device__ __forceinline__ float fast_sigmoid(float v) { return 1.0f / (1.0f + __expf(-v)); }
__device__ __forceinline__ float fast_tanh(float v) {
    return 1.0f - 2.0f / (__expf(2.0f * v) + 1.0f);   // exact +/-1 at large |v|
}

// ---------------- Kernel ----------------
__global__ void __launch_bounds__(THREADS)
lstm_mma_kernel(const float* __restrict__ x, const float* __restrict__ h,
                const float* __restrict__ c,
                const float* __restrict__ Wi, const float* __restrict__ bi,
                const float* __restrict__ Ui,
                const float* __restrict__ Wf, const float* __restrict__ bfv,
                const float* __restrict__ Uf,
                const float* __restrict__ Wo, const float* __restrict__ bo,
                const float* __restrict__ Uo,
                const float* __restrict__ Wc, const float* __restrict__ bc,
                const float* __restrict__ Uc,
                float* __restrict__ out_h, float* __restrict__ out_c) {
    extern __shared__ char smem[];
    float* smf = (float*)smem;

    const int tid  = threadIdx.x;
    const int wid  = tid >> 5;
    const int lane = tid & 31;
    const int warp_m = wid >> 2;      // 0..1  (64 rows each)
    const int warp_n = wid & 3;       // 0..3  (32 cols each)
    const int j0 = blockIdx.x * JBLK;
    const int m0 = blockIdx.y * TILE_M;

    // bias -> smem
    if (tid < 128) {
        const int g = tid >> 5, jj = tid & 31;
        const float* bp = (g == 0) ? bi : (g == 1) ? bfv : (g == 2) ? bo : bc;
        smf[SM_BIAS / 4 + tid] = bp[j0 + jj];
    }

    // ---------------- producer addressing ----------------
    const int rA  = tid >> 3;         // 0..31 : smem row (A: +32*i, B: one row per gate)
    const int seg = tid & 7;          // 0..7  : 4-float group within a 32-float row
    const int swg = (seg ^ (rA & 7)) << 2;   // swizzled group offset (floats)

    const float* ax = x + (size_t)(m0 + rA) * DH + seg * 4;
    const float* ah = h + (size_t)(m0 + rA) * DH + seg * 4;
    const float* bw[4] = { Wi + (size_t)(j0 + rA) * DH + seg * 4,
                           Wf + (size_t)(j0 + rA) * DH + seg * 4,
                           Wo + (size_t)(j0 + rA) * DH + seg * 4,
                           Wc + (size_t)(j0 + rA) * DH + seg * 4 };
    const float* bu[4] = { Ui + (size_t)(j0 + rA) * DH + seg * 4,
                           Uf + (size_t)(j0 + rA) * DH + seg * 4,
                           Uo + (size_t)(j0 + rA) * DH + seg * 4,
                           Uc + (size_t)(j0 + rA) * DH + seg * 4 };

    float4 ra[4], rb[4];
    // prologue: load chunk 0
    {
        const int k = 0;
#pragma unroll
        for (int i = 0; i < 4; i++)
            ra[i] = *(const float4*)(ax + (size_t)i * 32 * DH + k);
#pragma unroll
        for (int g = 0; g < 4; g++)
            rb[g] = *(const float4*)(bw[g] + k);
    }

    float acc[4][4][4];
#pragma unroll
    for (int mi = 0; mi < 4; mi++)
#pragma unroll
        for (int ni = 0; ni < 4; ni++)
#pragma unroll
            for (int r = 0; r < 4; r++) acc[mi][ni][r] = 0.0f;

    const int q  = lane >> 2;         // 0..7
    const int tg = lane & 3;          // 0..3
    const int ar0 = warp_m * 64 + q;
    const int bn0 = warp_n * 32 + q;

#pragma unroll 1
    for (int t = 0; t < NCHUNK; t++) {
        float* As = smf + SM_STAGE / 4 + (t & 1) * STAGE_FLOATS;
        float* Bs = As + A_FLOATS;

        // STS chunk t (convert to tf32 with round-to-nearest during staging)
#pragma unroll
        for (int i = 0; i < 4; i++) {
            uint4 w = { f2tf32(ra[i].x), f2tf32(ra[i].y), f2tf32(ra[i].z), f2tf32(ra[i].w) };
            *(uint4*)(As + (rA + 32 * i) * 32 + swg) = w;
        }
#pragma unroll
        for (int g = 0; g < 4; g++) {
            uint4 w = { f2tf32(rb[g].x), f2tf32(rb[g].y), f2tf32(rb[g].z), f2tf32(rb[g].w) };
            *(uint4*)(Bs + (g * 32 + rA) * 32 + swg) = w;
        }
        __syncthreads();

        // prefetch chunk t+1 (phase 0: x/W at k=t*32; phase 1: h/U at k=(t-32)*32)
        if (t + 1 < NCHUNK) {
            const int t1 = t + 1;
            const bool ph0 = (t1 < 32);
            const int k = (t1 & 31) * KCH;
            const float* Ab = ph0 ? ax : ah;
#pragma unroll
            for (int i = 0; i < 4; i++)
                ra[i] = *(const float4*)(Ab + (size_t)i * 32 * DH + k);
#pragma unroll
            for (int g = 0; g < 4; g++)
                rb[g] = *(const float4*)((ph0 ? bw[g] : bu[g]) + k);
        }

        // compute on chunk t
#pragma unroll
        for (int ks = 0; ks < 4; ks++) {
            const int c0 = (((2 * ks)     ^ q) << 2) | tg;
            const int c1 = (((2 * ks + 1) ^ q) << 2) | tg;
            uint32_t a[4][4], b[4][2];
#pragma unroll
            for (int mi = 0; mi < 4; mi++) {
                const int r1 = (ar0 + mi * 16) * 32;
                a[mi][0] = __float_as_uint(As[r1 + c0]);
                a[mi][1] = __float_as_uint(As[r1 + 8 * 32 + c0]);
                a[mi][2] = __float_as_uint(As[r1 + c1]);
                a[mi][3] = __float_as_uint(As[r1 + 8 * 32 + c1]);
            }
#pragma unroll
            for (int ni = 0; ni < 4; ni++) {
                const int n1 = (bn0 + ni * 8) * 32;
                b[ni][0] = __float_as_uint(Bs[n1 + c0]);
                b[ni][1] = __float_as_uint(Bs[n1 + c1]);
            }
#pragma unroll
            for (int mi = 0; mi < 4; mi++)
#pragma unroll
                for (int ni = 0; ni < 4; ni++)
                    mma_tf32(acc[mi][ni], a[mi], b[ni]);
        }
    }
    __syncthreads();   // everyone done reading stages; dump may alias them

    // ---------------- dump accumulators to smem ----------------
    {
        float* dump = smf + SM_STAGE / 4;
        const int dr = warp_m * 64 + q;
        const int dc = warp_n * 32 + tg * 2;
#pragma unroll
        for (int mi = 0; mi < 4; mi++)
#pragma unroll
            for (int ni = 0; ni < 4; ni++) {
                float2 v0 = { acc[mi][ni][0], acc[mi][ni][1] };
                float2 v1 = { acc[mi][ni][2], acc[mi][ni][3] };
                *(float2*)(dump + (dr + mi * 16) * DUMP_PITCH + dc + ni * 8) = v0;
                *(float2*)(dump + (dr + mi * 16 + 8) * DUMP_PITCH + dc + ni * 8) = v1;
            }
    }
    __syncthreads();

    // ---------------- fused LSTM epilogue ----------------
    {
        const float* dump = smf + SM_STAGE / 4;
        const float* bias = smf + SM_BIAS / 4;
        const int row8 = tid >> 3;
        const int jg = (tid & 7) * 4;
        const float4 bi4 = *(const float4*)(bias + jg);
        const float4 bf4 = *(const float4*)(bias + 32 + jg);
        const float4 bo4 = *(const float4*)(bias + 64 + jg);
        const float4 bc4 = *(const float4*)(bias + 96 + jg);
#pragma unroll
        for (int p = 0; p < 4; p++) {
            const int row = row8 + p * 32;
            const float4 gi = *(const float4*)(dump + row * DUMP_PITCH + jg);
            const float4 gf = *(const float4*)(dump + row * DUMP_PITCH + 32 + jg);
            const float4 go = *(const float4*)(dump + row * DUMP_PITCH + 64 + jg);
            const float4 gc = *(const float4*)(dump + row * DUMP_PITCH + 96 + jg);
            const size_t o = (size_t)(m0 + row) * DH + j0 + jg;
            const float4 ci = *(const float4*)(c + o);
            float4 nh, nc;
            {
                float ig = fast_sigmoid(gi.x + bi4.x), fg = fast_sigmoid(gf.x + bf4.x);
                float og = fast_sigmoid(go.x + bo4.x), cg = fast_tanh(gc.x + bc4.x);
                nc.x = fg * ci.x + ig * cg;  nh.x = og * fast_tanh(nc.x);
            }
            {
                float ig = fast_sigmoid(gi.y + bi4.y), fg = fast_sigmoid(gf.y + bf4.y);
                float og = fast_sigmoid(go.y + bo4.y), cg = fast_tanh(gc.y + bc4.y);
                nc.y = fg * ci.y + ig * cg;  nh.y = og * fast_tanh(nc.y);
            }
            {
                float ig = fast_sigmoid(gi.z + bi4.z), fg = fast_sigmoid(gf.z + bf4.z);
                float og = fast_sigmoid(go.z + bo4.z), cg = fast_tanh(gc.z + bc4.z);
                nc.z = fg * ci.z + ig * cg;  nh.z = og * fast_tanh(nc.z);
            }
            {
                float ig = fast_sigmoid(gi.w + bi4.w), fg = fast_sigmoid(gf.w + bf4.w);
                float og = fast_sigmoid(go.w + bo4.w), cg = fast_tanh(gc.w + bc4.w);
                nc.w = fg * ci.w + ig * cg;  nh.w = og * fast_tanh(nc.w);
            }
            *(float4*)(out_h + o) = nh;
            *(float4*)(out_c + o) = nc;
        }
    }
}

// ---------------- Host launch ----------------
extern "C" void kernel_launch(void* const* d_in, const int* in_sizes, int n_in,
                              void* d_out, int out_size) {
    const float* x  = (const float*)d_in[0];
    const float* h  = (const float*)d_in[1];
    const float* c  = (const float*)d_in[2];
    const float* Wi = (const float*)d_in[3];
    const float* bi = (const float*)d_in[4];
    const float* Ui = (const float*)d_in[5];
    const float* Wf = (const float*)d_in[6];
    const float* bf = (const float*)d_in[7];
    const float* Uf = (const float*)d_in[8];
    const float* Wo = (const float*)d_in[9];
    const float* bo = (const float*)d_in[10];
    const float* Uo = (const float*)d_in[11];
    const float* Wc = (const float*)d_in[12];
    const float* bc = (const float*)d_in[13];
    const float* Uc = (const float*)d_in[14];
    float* out_h = (float*)d_out;
    float* out_c = out_h + (size_t)BATCH * DH;

    static bool attr_set = false;
    if (!attr_set) {
        cudaFuncSetAttribute(lstm_mma_kernel, cudaFuncAttributeMaxDynamicSharedMemorySize,
                             SMEM_TOTAL);
        attr_set = true;
    }
    dim3 grid(DH / JBLK, BATCH / TILE_M);   // (32, 64)
    lstm_mma_kernel<<<grid, THREADS, SMEM_TOTAL>>>(x, h, c, Wi, bi, Ui, Wf, bf, Uf,
                                                   Wo, bo, Uo, Wc, bc, Uc, out_h, out_c);
}

// round 5
// speedup vs baseline: 1.7779x; 1.7779x over previous
#include <cuda_runtime.h>
#include <cstdint>

// ---------------- Problem constants ----------------
#define BATCH   8192
#define DH      1024
#define TILE_M  128             // batch rows per CTA
#define JBLK    32              // hidden cols per CTA (per gate)
#define KCH     32              // K elems per chunk (= 128B rows)
#define NCHUNK  64              // 2*1024/32
#define THREADS 256

// ---------------- tf32 scratch (pre-rounded inputs) ----------------
#define SCR_X 0u
#define SCR_H 8388608u
#define SCR_W 16777216u          // 8 matrices of 1048576, order Wi,Wf,Wo,Wc,Ui,Uf,Uo,Uc
__device__ float g_scr[25165824];   // ~100.7 MB static scratch (sanctioned workaround)

// ---------------- SMEM layout ----------------
// [0,512)   bias (4 gates x 32 floats)
// [512,..)  3 stages x (A 16KB + B 16KB) = 96KB ; epilogue dump (67.5KB) aliases stages
#define SM_STAGE_B  512
#define A_BYTES     16384
#define STAGE_BYTES 32768
#define DUMP_PITCH  132
#define SMEM_TOTAL  (512 + 3 * STAGE_BYTES)   // 98816 -> 2 CTAs/SM

// ---------------- helpers ----------------
__device__ __forceinline__ uint32_t smem_u32(const void* p) {
    uint32_t a;
    asm("{ .reg .u64 t; cvta.to.shared.u64 t, %1; cvt.u32.u64 %0, t; }" : "=r"(a) : "l"(p));
    return a;
}
__device__ __forceinline__ uint32_t f2tf32(float f) {
    uint32_t u;
    asm("cvt.rna.tf32.f32 %0, %1;" : "=r"(u) : "f"(f));
    return u;
}
__device__ __forceinline__ void mma_tf32(float* d, const uint32_t* a, const uint32_t* b) {
    asm volatile(
        "mma.sync.aligned.m16n8k8.row.col.f32.tf32.tf32.f32 "
        "{%0,%1,%2,%3}, {%4,%5,%6,%7}, {%8,%9}, {%0,%1,%2,%3};"
        : "+f"(d[0]), "+f"(d[1]), "+f"(d[2]), "+f"(d[3])
        : "r"(a[0]), "r"(a[1]), "r"(a[2]), "r"(a[3]), "r"(b[0]), "r"(b[1]));
}
#define LDSM4(r, addr)                                                            \
    asm volatile("ldmatrix.sync.aligned.m8n8.x4.shared.b16 {%0,%1,%2,%3}, [%4];"  \
        : "=r"((r)[0]), "=r"((r)[1]), "=r"((r)[2]), "=r"((r)[3]) : "r"(addr))
#define CP_ASYNC16(dst, src) \
    asm volatile("cp.async.cg.shared.global [%0], [%1], 16;" :: "r"(dst), "l"(src))
#define CP_COMMIT()  asm volatile("cp.async.commit_group;" ::: "memory")
#define CP_WAIT(n)   asm volatile("cp.async.wait_group %0;" :: "n"(n) : "memory")

__device__ __forceinline__ float fast_sigmoid(float v) { return 1.0f / (1.0f + __expf(-v)); }
__device__ __forceinline__ float fast_tanh(float v) {
    return 1.0f - 2.0f / (__expf(2.0f * v) + 1.0f);   // exact +/-1 at large |v|
}

// ---------------- rounding pass kernels ----------------
__global__ void __launch_bounds__(THREADS)
round_xh_kernel(const float* __restrict__ x, const float* __restrict__ h) {
    const size_t i = ((size_t)blockIdx.x * THREADS + threadIdx.x) * 4;
    float4 vx = *(const float4*)(x + i);
    float4 vh = *(const float4*)(h + i);
    uint4 wx = { f2tf32(vx.x), f2tf32(vx.y), f2tf32(vx.z), f2tf32(vx.w) };
    uint4 wh = { f2tf32(vh.x), f2tf32(vh.y), f2tf32(vh.z), f2tf32(vh.w) };
    *(uint4*)(g_scr + SCR_X + i) = wx;
    *(uint4*)(g_scr + SCR_H + i) = wh;
}
__global__ void __launch_bounds__(THREADS)
round_w_kernel(const float* __restrict__ p0, const float* __restrict__ p1,
               const float* __restrict__ p2, const float* __restrict__ p3,
               const float* __restrict__ p4, const float* __restrict__ p5,
               const float* __restrict__ p6, const float* __restrict__ p7) {
    const int g = blockIdx.y;
    const float* src = (g == 0) ? p0 : (g == 1) ? p1 : (g == 2) ? p2 : (g == 3) ? p3
                      : (g == 4) ? p4 : (g == 5) ? p5 : (g == 6) ? p6 : p7;
    const size_t i = ((size_t)blockIdx.x * THREADS + threadIdx.x) * 4;
    float4 v = *(const float4*)(src + i);
    uint4 w = { f2tf32(v.x), f2tf32(v.y), f2tf32(v.z), f2tf32(v.w) };
    *(uint4*)(g_scr + SCR_W + (size_t)g * 1048576 + i) = w;
}

// ---------------- stage producer ----------------
__device__ __forceinline__ void issue_stage(uint32_t st, int tt, uint32_t dA,
                                            const float* gsA0, const float* gsA1,
                                            const float* gsB) {
    const int p = tt >> 5;
    const int k = (tt & 31) * KCH;
    const float* sa = (p ? gsA1 : gsA0) + k;
    const float* sw = gsB + (size_t)p * 4194304 + k;
#pragma unroll
    for (int i = 0; i < 4; i++)          // A rows rA + 32*i
        CP_ASYNC16(st + dA + i * 4096, sa + (size_t)i * 32768);
#pragma unroll
    for (int g = 0; g < 4; g++)          // B rows g*32 + rA (gate-major)
        CP_ASYNC16(st + A_BYTES + dA + g * 4096, sw + (size_t)g * 1048576);
}

// ---------------- GEMM + fused LSTM kernel ----------------
__global__ void __launch_bounds__(THREADS, 2)
lstm_mma2_kernel(const float* __restrict__ bi, const float* __restrict__ bfv,
                 const float* __restrict__ bo, const float* __restrict__ bc,
                 const float* __restrict__ c,
                 float* __restrict__ out_h, float* __restrict__ out_c) {
    extern __shared__ char smem[];
    float* smf = (float*)smem;
    const uint32_t sb = smem_u32(smem);

    const int tid  = threadIdx.x;
    const int wid  = tid >> 5;
    const int lane = tid & 31;
    const int warp_m = wid >> 2;      // 0..1 (64 rows each)
    const int warp_n = wid & 3;       // 0..3 (= gate, 32 cols each)
    const int j0 = blockIdx.x * JBLK;
    const int m0 = blockIdx.y * TILE_M;

    // bias -> smem [g*32 + jj]
    if (tid < 128) {
        const int g = tid >> 5, jj = tid & 31;
        const float* bp = (g == 0) ? bi : (g == 1) ? bfv : (g == 2) ? bo : bc;
        smf[tid] = bp[j0 + jj];
    }

    // -------- producer addressing (cp.async) --------
    const int rA  = tid >> 3;                 // 0..31
    const int seg = tid & 7;                  // 16B granule within 128B row
    const uint32_t dA = (uint32_t)(rA * 128 + ((seg ^ (rA & 7)) << 4));
    const float* gsA0 = g_scr + SCR_X + (size_t)(m0 + rA) * DH + seg * 4;
    const float* gsA1 = g_scr + SCR_H + (size_t)(m0 + rA) * DH + seg * 4;
    const float* gsB  = g_scr + SCR_W + (size_t)(j0 + rA) * DH + seg * 4;

    // -------- consumer (ldmatrix) addressing --------
    // A frag (m16 x k8): lanes 0-7 rows+0..7 g, 8-15 rows+8..15 g, 16-23 rows+0..7 g+1, 24-31 rows+8..15 g+1
    const uint32_t l7x   = (uint32_t)((lane & 7) << 4);
    const int rowA_off   = (lane & 7) + ((lane >> 3) & 1) * 8;
    const uint32_t goffA = (lane >> 4) & 1;
    const uint32_t aoffb = (uint32_t)((warp_m * 64 + rowA_off) * 128);
    // B frag pair (n16 x k8): lanes 0-7 rows+0..7 g, 8-15 rows+0..7 g+1, 16-23 rows+8..15 g, 24-31 rows+8..15 g+1
    const int rowB_off   = (lane & 7) + ((lane >> 4) & 1) * 8;
    const uint32_t goffB = (lane >> 3) & 1;
    const uint32_t boffb = (uint32_t)(A_BYTES + (warp_n * 32 + rowB_off) * 128);

    float acc[4][4][4];
#pragma unroll
    for (int mi = 0; mi < 4; mi++)
#pragma unroll
        for (int ni = 0; ni < 4; ni++)
#pragma unroll
            for (int r = 0; r < 4; r++) acc[mi][ni][r] = 0.0f;

    // -------- prologue: stages 0,1 --------
    issue_stage(sb + SM_STAGE_B + 0 * STAGE_BYTES, 0, dA, gsA0, gsA1, gsB);
    CP_COMMIT();
    issue_stage(sb + SM_STAGE_B + 1 * STAGE_BYTES, 1, dA, gsA0, gsA1, gsB);
    CP_COMMIT();

    // -------- main loop --------
    int s = 0;   // compute buffer
    int u = 2;   // fill buffer
#pragma unroll 1
    for (int t = 0; t < NCHUNK; t++) {
        CP_WAIT(1);          // stage t landed (this thread's copies)
        __syncthreads();     // all threads: stage t ready AND done with stage t-1
        if (t + 2 < NCHUNK)
            issue_stage(sb + SM_STAGE_B + u * STAGE_BYTES, t + 2, dA, gsA0, gsA1, gsB);
        CP_COMMIT();

        const uint32_t st = sb + SM_STAGE_B + s * STAGE_BYTES;
#pragma unroll
        for (int ks = 0; ks < 4; ks++) {
            const uint32_t tA = (uint32_t)((2 * ks + goffA) << 4);
            const uint32_t tB = (uint32_t)((2 * ks + goffB) << 4);
            uint32_t b[8];
            LDSM4(b + 0, st + boffb + 0    + (tB ^ l7x));   // ni 0,1
            LDSM4(b + 4, st + boffb + 2048 + (tB ^ l7x));   // ni 2,3
#pragma unroll
            for (int mi = 0; mi < 4; mi++) {
                uint32_t a[4];
                LDSM4(a, st + aoffb + mi * 2048 + (tA ^ l7x));
                mma_tf32(acc[mi][0], a, b + 0);
                mma_tf32(acc[mi][1], a, b + 2);
                mma_tf32(acc[mi][2], a, b + 4);
                mma_tf32(acc[mi][3], a, b + 6);
            }
        }
        s = (s == 2) ? 0 : s + 1;
        u = (u == 2) ? 0 : u + 1;
    }
    CP_WAIT(0);
    __syncthreads();   // stages dead; dump may alias them

    // -------- dump accumulators to smem --------
    {
        float* dump = smf + 128;    // byte 512
        const int q  = lane >> 2;
        const int tg = lane & 3;
        const int dr = warp_m * 64 + q;
        const int dc = warp_n * 32 + tg * 2;
#pragma unroll
        for (int mi = 0; mi < 4; mi++)
#pragma unroll
            for (int ni = 0; ni < 4; ni++) {
                float2 v0 = { acc[mi][ni][0], acc[mi][ni][1] };
                float2 v1 = { acc[mi][ni][2], acc[mi][ni][3] };
                *(float2*)(dump + (dr + mi * 16) * DUMP_PITCH + dc + ni * 8) = v0;
                *(float2*)(dump + (dr + mi * 16 + 8) * DUMP_PITCH + dc + ni * 8) = v1;
            }
    }
    __syncthreads();

    // -------- fused LSTM epilogue --------
    {
        const float* dump = smf + 128;
        const float* bias = smf;
        const int row8 = tid >> 3;
        const int jg = (tid & 7) * 4;
        const float4 bi4 = *(const float4*)(bias + jg);
        const float4 bf4 = *(const float4*)(bias + 32 + jg);
        const float4 bo4 = *(const float4*)(bias + 64 + jg);
        const float4 bc4 = *(const float4*)(bias + 96 + jg);
#pragma unroll
        for (int p = 0; p < 4; p++) {
            const int row = row8 + p * 32;
            const float4 gi = *(const float4*)(dump + row * DUMP_PITCH + jg);
            const float4 gf = *(const float4*)(dump + row * DUMP_PITCH + 32 + jg);
            const float4 go = *(const float4*)(dump + row * DUMP_PITCH + 64 + jg);
            const float4 gc = *(const float4*)(dump + row * DUMP_PITCH + 96 + jg);
            const size_t o = (size_t)(m0 + row) * DH + j0 + jg;
            const float4 ci = *(const float4*)(c + o);
            float4 nh, nc;
            {
                float ig = fast_sigmoid(gi.x + bi4.x), fg = fast_sigmoid(gf.x + bf4.x);
                float og = fast_sigmoid(go.x + bo4.x), cg = fast_tanh(gc.x + bc4.x);
                nc.x = fg * ci.x + ig * cg;  nh.x = og * fast_tanh(nc.x);
            }
            {
                float ig = fast_sigmoid(gi.y + bi4.y), fg = fast_sigmoid(gf.y + bf4.y);
                float og = fast_sigmoid(go.y + bo4.y), cg = fast_tanh(gc.y + bc4.y);
                nc.y = fg * ci.y + ig * cg;  nh.y = og * fast_tanh(nc.y);
            }
            {
                float ig = fast_sigmoid(gi.z + bi4.z), fg = fast_sigmoid(gf.z + bf4.z);
                float og = fast_sigmoid(go.z + bo4.z), cg = fast_tanh(gc.z + bc4.z);
                nc.z = fg * ci.z + ig * cg;  nh.z = og * fast_tanh(nc.z);
            }
            {
                float ig = fast_sigmoid(gi.w + bi4.w), fg = fast_sigmoid(gf.w + bf4.w);
                float og = fast_sigmoid(go.w + bo4.w), cg = fast_tanh(gc.w + bc4.w);
                nc.w = fg * ci.w + ig * cg;  nh.w = og * fast_tanh(nc.w);
            }
            *(float4*)(out_h + o) = nh;
            *(float4*)(out_c + o) = nc;
        }
    }
}

// ---------------- Host launch ----------------
extern "C" void kernel_launch(void* const* d_in, const int* in_sizes, int n_in,
                              void* d_out, int out_size) {
    const float* x  = (const float*)d_in[0];
    const float* h  = (const float*)d_in[1];
    const float* c  = (const float*)d_in[2];
    const float* Wi = (const float*)d_in[3];
    const float* bi = (const float*)d_in[4];
    const float* Ui = (const float*)d_in[5];
    const float* Wf = (const float*)d_in[6];
    const float* bf = (const float*)d_in[7];
    const float* Uf = (const float*)d_in[8];
    const float* Wo = (const float*)d_in[9];
    const float* bo = (const float*)d_in[10];
    const float* Uo = (const float*)d_in[11];
    const float* Wc = (const float*)d_in[12];
    const float* bc = (const float*)d_in[13];
    const float* Uc = (const float*)d_in[14];
    float* out_h = (float*)d_out;
    float* out_c = out_h + (size_t)BATCH * DH;

    static bool once = false;
    if (!once) {
        cudaFuncSetAttribute(lstm_mma2_kernel, cudaFuncAttributeMaxDynamicSharedMemorySize,
                             SMEM_TOTAL);
        once = true;
    }

    // 1) round inputs to tf32 into scratch
    round_xh_kernel<<<8192, THREADS>>>(x, h);
    dim3 gw(1024, 8);
    round_w_kernel<<<gw, THREADS>>>(Wi, Wf, Wo, Wc, Ui, Uf, Uo, Uc);

    // 2) GEMM + fused gates
    dim3 grid(DH / JBLK, BATCH / TILE_M);   // (32, 64)
    lstm_mma2_kernel<<<grid, THREADS, SMEM_TOTAL>>>(bi, bf, bo, bc, c, out_h, out_c);
}

// round 6
// speedup vs baseline: 2.1258x; 1.1957x over previous
#include <cuda_runtime.h>
#include <cuda_fp16.h>
#include <cstdint>

// ---------------- Problem constants ----------------
#define BATCH   8192
#define DH      1024
#define TILE_M  128             // batch rows per CTA
#define JBLK    32              // hidden cols per CTA (per gate)
#define KCH     64              // K elems per chunk (fp16: 128B rows)
#define NCHUNK  32              // 2*1024/64
#define THREADS 256

// ---------------- fp16 scratch (pre-rounded inputs), offsets in halfs ----------------
#define SCR_X 0u
#define SCR_H 8388608u
#define SCR_W 16777216u          // 8 matrices of 1048576 halfs: Wi,Wf,Wo,Wc,Ui,Uf,Uo,Uc
__device__ __half g_scrh[25165824];   // ~50.3 MB static scratch

// ---------------- SMEM layout ----------------
// [0,512)  bias (4 gates x 32 floats); [512,..) 3 stages x (A 16KB + B 16KB)
// epilogue dump (128 x 132 floats) aliases the stages
#define SM_STAGE_B  512
#define A_BYTES     16384
#define STAGE_BYTES 32768
#define DUMP_PITCH  132
#define SMEM_TOTAL  (512 + 3 * STAGE_BYTES)   // 98816 -> 2 CTAs/SM

// ---------------- helpers ----------------
__device__ __forceinline__ uint32_t smem_u32(const void* p) {
    uint32_t a;
    asm("{ .reg .u64 t; cvta.to.shared.u64 t, %1; cvt.u32.u64 %0, t; }" : "=r"(a) : "l"(p));
    return a;
}
__device__ __forceinline__ void mma_f16(float* d, const uint32_t* a, const uint32_t* b) {
    asm volatile(
        "mma.sync.aligned.m16n8k16.row.col.f32.f16.f16.f32 "
        "{%0,%1,%2,%3}, {%4,%5,%6,%7}, {%8,%9}, {%0,%1,%2,%3};"
        : "+f"(d[0]), "+f"(d[1]), "+f"(d[2]), "+f"(d[3])
        : "r"(a[0]), "r"(a[1]), "r"(a[2]), "r"(a[3]), "r"(b[0]), "r"(b[1]));
}
#define LDSM4(r, addr)                                                            \
    asm volatile("ldmatrix.sync.aligned.m8n8.x4.shared.b16 {%0,%1,%2,%3}, [%4];"  \
        : "=r"((r)[0]), "=r"((r)[1]), "=r"((r)[2]), "=r"((r)[3]) : "r"(addr))
#define CP_ASYNC16(dst, src) \
    asm volatile("cp.async.cg.shared.global [%0], [%1], 16;" :: "r"(dst), "l"(src))
#define CP_COMMIT()  asm volatile("cp.async.commit_group;" ::: "memory")
#define CP_WAIT(n)   asm volatile("cp.async.wait_group %0;" :: "n"(n) : "memory")

__device__ __forceinline__ float fast_sigmoid(float v) { return 1.0f / (1.0f + __expf(-v)); }
__device__ __forceinline__ float fast_tanh(float v) {
    return 1.0f - 2.0f / (__expf(2.0f * v) + 1.0f);   // exact +/-1 at large |v|
}

// ---------------- rounding pass kernels (fp32 -> fp16 RN) ----------------
__global__ void __launch_bounds__(THREADS)
round_xh_kernel(const float* __restrict__ x, const float* __restrict__ h) {
    const size_t i = ((size_t)blockIdx.x * THREADS + threadIdx.x) * 4;
    float4 vx = *(const float4*)(x + i);
    float4 vh = *(const float4*)(h + i);
    __half2 x01 = __floats2half2_rn(vx.x, vx.y), x23 = __floats2half2_rn(vx.z, vx.w);
    __half2 h01 = __floats2half2_rn(vh.x, vh.y), h23 = __floats2half2_rn(vh.z, vh.w);
    uint2 wx = { *(uint32_t*)&x01, *(uint32_t*)&x23 };
    uint2 wh = { *(uint32_t*)&h01, *(uint32_t*)&h23 };
    *(uint2*)(g_scrh + SCR_X + i) = wx;
    *(uint2*)(g_scrh + SCR_H + i) = wh;
}
__global__ void __launch_bounds__(THREADS)
round_w_kernel(const float* __restrict__ p0, const float* __restrict__ p1,
               const float* __restrict__ p2, const float* __restrict__ p3,
               const float* __restrict__ p4, const float* __restrict__ p5,
               const float* __restrict__ p6, const float* __restrict__ p7) {
    const int g = blockIdx.y;
    const float* src = (g == 0) ? p0 : (g == 1) ? p1 : (g == 2) ? p2 : (g == 3) ? p3
                      : (g == 4) ? p4 : (g == 5) ? p5 : (g == 6) ? p6 : p7;
    const size_t i = ((size_t)blockIdx.x * THREADS + threadIdx.x) * 4;
    float4 v = *(const float4*)(src + i);
    __half2 v01 = __floats2half2_rn(v.x, v.y), v23 = __floats2half2_rn(v.z, v.w);
    uint2 w = { *(uint32_t*)&v01, *(uint32_t*)&v23 };
    *(uint2*)(g_scrh + SCR_W + (size_t)g * 1048576 + i) = w;
}

// ---------------- stage producer ----------------
__device__ __forceinline__ void issue_stage(uint32_t st, int tt, uint32_t dA,
                                            const __half* gsA0, const __half* gsA1,
                                            const __half* gsB) {
    const int p = tt >> 4;               // 0: x/W, 1: h/U
    const int k = (tt & 15) * KCH;
    const __half* sa = (p ? gsA1 : gsA0) + k;
    const __half* sw = gsB + (size_t)p * 4194304 + k;
#pragma unroll
    for (int i = 0; i < 4; i++)          // A rows rA + 32*i (row stride 1024 halfs)
        CP_ASYNC16(st + dA + i * 4096, sa + (size_t)i * 32768);
#pragma unroll
    for (int g = 0; g < 4; g++)          // B rows g*32 + rA (gate-major)
        CP_ASYNC16(st + A_BYTES + dA + g * 4096, sw + (size_t)g * 1048576);
}

// ---------------- GEMM + fused LSTM kernel ----------------
__global__ void __launch_bounds__(THREADS, 2)
lstm_mma3_kernel(const float* __restrict__ bi, const float* __restrict__ bfv,
                 const float* __restrict__ bo, const float* __restrict__ bc,
                 const float* __restrict__ c,
                 float* __restrict__ out_h, float* __restrict__ out_c) {
    extern __shared__ char smem[];
    float* smf = (float*)smem;
    const uint32_t sb = smem_u32(smem);

    const int tid  = threadIdx.x;
    const int wid  = tid >> 5;
    const int lane = tid & 31;
    const int warp_m = wid >> 2;      // 0..1 (64 rows each)
    const int warp_n = wid & 3;       // 0..3 (= gate, 32 cols each)
    const int j0 = blockIdx.x * JBLK;
    const int m0 = blockIdx.y * TILE_M;

    // bias -> smem [g*32 + jj]
    if (tid < 128) {
        const int g = tid >> 5, jj = tid & 31;
        const float* bp = (g == 0) ? bi : (g == 1) ? bfv : (g == 2) ? bo : bc;
        smf[tid] = bp[j0 + jj];
    }

    // -------- producer addressing (cp.async) --------
    const int rA  = tid >> 3;                 // 0..31
    const int seg = tid & 7;                  // 16B granule within 128B row
    const uint32_t dA = (uint32_t)(rA * 128 + ((seg ^ (rA & 7)) << 4));
    const __half* gsA0 = g_scrh + SCR_X + (size_t)(m0 + rA) * DH + seg * 8;
    const __half* gsA1 = g_scrh + SCR_H + (size_t)(m0 + rA) * DH + seg * 8;
    const __half* gsB  = g_scrh + SCR_W + (size_t)(j0 + rA) * DH + seg * 8;

    // -------- consumer (ldmatrix) addressing --------
    const uint32_t l7x = (uint32_t)((lane & 7) << 4);   // swizzle XOR term
    // A m16xk16 frag: lanes 0-7 m0-7/k0, 8-15 m8-15/k0, 16-23 m0-7/k8, 24-31 m8-15/k8
    const uint32_t aoffb = (uint32_t)((warp_m * 64 + (lane & 15)) * 128);
    const uint32_t koffA = (uint32_t)((lane >> 4) << 4);
    // B n16xk16 frag: lanes 0-7 n0-7/k0, 8-15 n0-7/k8, 16-23 n8-15/k0, 24-31 n8-15/k8
    const uint32_t boffb = (uint32_t)(A_BYTES +
                          (warp_n * 32 + (lane & 7) + (((lane >> 4) & 1) << 3)) * 128);
    const uint32_t koffB = (uint32_t)(((lane >> 3) & 1) << 4);

    float acc[4][4][4];
#pragma unroll
    for (int mi = 0; mi < 4; mi++)
#pragma unroll
        for (int ni = 0; ni < 4; ni++)
#pragma unroll
            for (int r = 0; r < 4; r++) acc[mi][ni][r] = 0.0f;

    // -------- prologue: stages 0,1 --------
    issue_stage(sb + SM_STAGE_B + 0 * STAGE_BYTES, 0, dA, gsA0, gsA1, gsB);
    CP_COMMIT();
    issue_stage(sb + SM_STAGE_B + 1 * STAGE_BYTES, 1, dA, gsA0, gsA1, gsB);
    CP_COMMIT();

    // -------- main loop --------
    int s = 0;   // compute buffer
    int u = 2;   // fill buffer
#pragma unroll 1
    for (int t = 0; t < NCHUNK; t++) {
        CP_WAIT(1);
        __syncthreads();
        if (t + 2 < NCHUNK)
            issue_stage(sb + SM_STAGE_B + u * STAGE_BYTES, t + 2, dA, gsA0, gsA1, gsB);
        CP_COMMIT();

        const uint32_t st = sb + SM_STAGE_B + s * STAGE_BYTES;
#pragma unroll
        for (int ks = 0; ks < 4; ks++) {          // 4 x k16 per 64-wide chunk
            const uint32_t tA = (uint32_t)(ks * 32 + koffA) ^ l7x;
            const uint32_t tB = (uint32_t)(ks * 32 + koffB) ^ l7x;
            uint32_t b0[4], b1[4];
            LDSM4(b0, st + boffb + tB);           // ni 0,1 (n0-15)
            LDSM4(b1, st + boffb + 2048 + tB);    // ni 2,3 (n16-31)
#pragma unroll
            for (int mi = 0; mi < 4; mi++) {
                uint32_t a[4];
                LDSM4(a, st + aoffb + mi * 2048 + tA);
                mma_f16(acc[mi][0], a, b0 + 0);
                mma_f16(acc[mi][1], a, b0 + 2);
                mma_f16(acc[mi][2], a, b1 + 0);
                mma_f16(acc[mi][3], a, b1 + 2);
            }
        }
        s = (s == 2) ? 0 : s + 1;
        u = (u == 2) ? 0 : u + 1;
    }
    CP_WAIT(0);
    __syncthreads();   // stages dead; dump may alias them

    // -------- dump accumulators to smem --------
    {
        float* dump = smf + 128;    // byte 512
        const int q  = lane >> 2;
        const int tg = lane & 3;
        const int dr = warp_m * 64 + q;
        const int dc = warp_n * 32 + tg * 2;
#pragma unroll
        for (int mi = 0; mi < 4; mi++)
#pragma unroll
            for (int ni = 0; ni < 4; ni++) {
                float2 v0 = { acc[mi][ni][0], acc[mi][ni][1] };
                float2 v1 = { acc[mi][ni][2], acc[mi][ni][3] };
                *(float2*)(dump + (dr + mi * 16) * DUMP_PITCH + dc + ni * 8) = v0;
                *(float2*)(dump + (dr + mi * 16 + 8) * DUMP_PITCH + dc + ni * 8) = v1;
            }
    }
    __syncthreads();

    // -------- fused LSTM epilogue --------
    {
        const float* dump = smf + 128;
        const float* bias = smf;
        const int row8 = tid >> 3;
        const int jg = (tid & 7) * 4;
        const float4 bi4 = *(const float4*)(bias + jg);
        const float4 bf4 = *(const float4*)(bias + 32 + jg);
        const float4 bo4 = *(const float4*)(bias + 64 + jg);
        const float4 bc4 = *(const float4*)(bias + 96 + jg);
#pragma unroll
        for (int p = 0; p < 4; p++) {
            const int row = row8 + p * 32;
            const float4 gi = *(const float4*)(dump + row * DUMP_PITCH + jg);
            const float4 gf = *(const float4*)(dump + row * DUMP_PITCH + 32 + jg);
            const float4 go = *(const float4*)(dump + row * DUMP_PITCH + 64 + jg);
            const float4 gc = *(const float4*)(dump + row * DUMP_PITCH + 96 + jg);
            const size_t o = (size_t)(m0 + row) * DH + j0 + jg;
            const float4 ci = *(const float4*)(c + o);
            float4 nh, nc;
            {
                float ig = fast_sigmoid(gi.x + bi4.x), fg = fast_sigmoid(gf.x + bf4.x);
                float og = fast_sigmoid(go.x + bo4.x), cg = fast_tanh(gc.x + bc4.x);
                nc.x = fg * ci.x + ig * cg;  nh.x = og * fast_tanh(nc.x);
            }
            {
                float ig = fast_sigmoid(gi.y + bi4.y), fg = fast_sigmoid(gf.y + bf4.y);
                float og = fast_sigmoid(go.y + bo4.y), cg = fast_tanh(gc.y + bc4.y);
                nc.y = fg * ci.y + ig * cg;  nh.y = og * fast_tanh(nc.y);
            }
            {
                float ig = fast_sigmoid(gi.z + bi4.z), fg = fast_sigmoid(gf.z + bf4.z);
                float og = fast_sigmoid(go.z + bo4.z), cg = fast_tanh(gc.z + bc4.z);
                nc.z = fg * ci.z + ig * cg;  nh.z = og * fast_tanh(nc.z);
            }
            {
                float ig = fast_sigmoid(gi.w + bi4.w), fg = fast_sigmoid(gf.w + bf4.w);
                float og = fast_sigmoid(go.w + bo4.w), cg = fast_tanh(gc.w + bc4.w);
                nc.w = fg * ci.w + ig * cg;  nh.w = og * fast_tanh(nc.w);
            }
            *(float4*)(out_h + o) = nh;
            *(float4*)(out_c + o) = nc;
        }
    }
}

// ---------------- Host launch ----------------
extern "C" void kernel_launch(void* const* d_in, const int* in_sizes, int n_in,
                              void* d_out, int out_size) {
    const float* x  = (const float*)d_in[0];
    const float* h  = (const float*)d_in[1];
    const float* c  = (const float*)d_in[2];
    const float* Wi = (const float*)d_in[3];
    const float* bi = (const float*)d_in[4];
    const float* Ui = (const float*)d_in[5];
    const float* Wf = (const float*)d_in[6];
    const float* bf = (const float*)d_in[7];
    const float* Uf = (const float*)d_in[8];
    const float* Wo = (const float*)d_in[9];
    const float* bo = (const float*)d_in[10];
    const float* Uo = (const float*)d_in[11];
    const float* Wc = (const float*)d_in[12];
    const float* bc = (const float*)d_in[13];
    const float* Uc = (const float*)d_in[14];
    float* out_h = (float*)d_out;
    float* out_c = out_h + (size_t)BATCH * DH;

    static bool once = false;
    if (!once) {
        cudaFuncSetAttribute(lstm_mma3_kernel, cudaFuncAttributeMaxDynamicSharedMemorySize,
                             SMEM_TOTAL);
        once = true;
    }

    // 1) round inputs to fp16 into scratch
    round_xh_kernel<<<8192, THREADS>>>(x, h);
    dim3 gw(1024, 8);
    round_w_kernel<<<gw, THREADS>>>(Wi, Wf, Wo, Wc, Ui, Uf, Uo, Uc);

    // 2) GEMM + fused gates
    dim3 grid(DH / JBLK, BATCH / TILE_M);   // (32, 64)
    lstm_mma3_kernel<<<grid, THREADS, SMEM_TOTAL>>>(bi, bf, bo, bc, c, out_h, out_c);
}

// round 7
// speedup vs baseline: 3.2578x; 1.5325x over previous
#include <cuda_runtime.h>
#include <cuda_fp16.h>
#include <cstdint>

// ---------------- Problem constants ----------------
#define BATCH   8192
#define DH      1024
#define TILE_M  128             // batch rows per CTA
#define JBLK    32              // hidden cols per CTA (per gate)
#define KCH     64              // K elems per chunk (fp16: 128B rows)
#define NCHUNK  32              // 2*1024/64
#define THREADS 256

// ---------------- fp16 scratch (pre-rounded inputs), offsets in halfs ----------------
#define SCR_X 0u
#define SCR_H 8388608u
#define SCR_W 16777216u          // 8 matrices of 1048576 halfs: Wi,Wf,Wo,Wc,Ui,Uf,Uo,Uc
__device__ __half g_scrh[25165824];   // ~50.3 MB static scratch

// ---------------- SMEM layout ----------------
// [0,512)  bias (4 gates x 32 floats); [512,..) 3 stages x (A 16KB + B 16KB)
// epilogue: dump 128x132 floats at byte 512 (aliases stages 0/1 + 2KB of stage 2);
//           c tile 16KB at byte 70144 (inside stage 2, clear of the dump)
#define SM_STAGE_B  512
#define A_BYTES     16384
#define STAGE_BYTES 32768
#define DUMP_PITCH  132
#define SM_C_BYTES  70144
#define SMEM_TOTAL  (512 + 3 * STAGE_BYTES)   // 98816 -> 2 CTAs/SM

// ---------------- helpers ----------------
__device__ __forceinline__ uint32_t smem_u32(const void* p) {
    uint32_t a;
    asm("{ .reg .u64 t; cvta.to.shared.u64 t, %1; cvt.u32.u64 %0, t; }" : "=r"(a) : "l"(p));
    return a;
}
__device__ __forceinline__ void mma_f16(float* d, const uint32_t* a, const uint32_t* b) {
    asm volatile(
        "mma.sync.aligned.m16n8k16.row.col.f32.f16.f16.f32 "
        "{%0,%1,%2,%3}, {%4,%5,%6,%7}, {%8,%9}, {%0,%1,%2,%3};"
        : "+f"(d[0]), "+f"(d[1]), "+f"(d[2]), "+f"(d[3])
        : "r"(a[0]), "r"(a[1]), "r"(a[2]), "r"(a[3]), "r"(b[0]), "r"(b[1]));
}
#define LDSM4(r, addr)                                                            \
    asm volatile("ldmatrix.sync.aligned.m8n8.x4.shared.b16 {%0,%1,%2,%3}, [%4];"  \
        : "=r"((r)[0]), "=r"((r)[1]), "=r"((r)[2]), "=r"((r)[3]) : "r"(addr))
#define CP_ASYNC16(dst, src) \
    asm volatile("cp.async.cg.shared.global [%0], [%1], 16;" :: "r"(dst), "l"(src))
#define CP_COMMIT()  asm volatile("cp.async.commit_group;" ::: "memory")
#define CP_WAIT(n)   asm volatile("cp.async.wait_group %0;" :: "n"(n) : "memory")

__device__ __forceinline__ float fast_sigmoid(float v) { return 1.0f / (1.0f + __expf(-v)); }
__device__ __forceinline__ float fast_tanh(float v) {
    return 1.0f - 2.0f / (__expf(2.0f * v) + 1.0f);   // exact +/-1 at large |v|
}

// ---------------- merged rounding pass (fp32 -> fp16 RN), one launch ----------------
// 24 regions of 1M floats: [0,8)=x, [8,16)=h, [16,24)=weights. 1024 blocks/region.
__global__ void __launch_bounds__(THREADS)
round_all_kernel(const float* __restrict__ x, const float* __restrict__ h,
                 const float* __restrict__ p0, const float* __restrict__ p1,
                 const float* __restrict__ p2, const float* __restrict__ p3,
                 const float* __restrict__ p4, const float* __restrict__ p5,
                 const float* __restrict__ p6, const float* __restrict__ p7) {
    const int r  = blockIdx.x >> 10;
    const int bi = blockIdx.x & 1023;
    const size_t off = ((size_t)bi * THREADS + threadIdx.x) * 4;
    const float* src;
    size_t dst;
    if (r < 8) {
        src = x + (((size_t)r) << 20) + off;
        dst = SCR_X + (((size_t)r) << 20) + off;
    } else if (r < 16) {
        src = h + (((size_t)(r - 8)) << 20) + off;
        dst = SCR_H + (((size_t)(r - 8)) << 20) + off;
    } else {
        const int g = r - 16;
        const float* wp = (g == 0) ? p0 : (g == 1) ? p1 : (g == 2) ? p2 : (g == 3) ? p3
                         : (g == 4) ? p4 : (g == 5) ? p5 : (g == 6) ? p6 : p7;
        src = wp + off;
        dst = SCR_W + (((size_t)g) << 20) + off;
    }
    float4 v = *(const float4*)src;
    __half2 v01 = __floats2half2_rn(v.x, v.y), v23 = __floats2half2_rn(v.z, v.w);
    uint2 w = { *(uint32_t*)&v01, *(uint32_t*)&v23 };
    *(uint2*)(g_scrh + dst) = w;
}

// ---------------- stage producer ----------------
__device__ __forceinline__ void issue_stage(uint32_t st, int tt, uint32_t dA,
                                            const __half* gsA0, const __half* gsA1,
                                            const __half* gsB) {
    const int p = tt >> 4;               // 0: x/W, 1: h/U
    const int k = (tt & 15) * KCH;
    const __half* sa = (p ? gsA1 : gsA0) + k;
    const __half* sw = gsB + (size_t)p * 4194304 + k;
#pragma unroll
    for (int i = 0; i < 4; i++)          // A rows rA + 32*i (row stride 1024 halfs)
        CP_ASYNC16(st + dA + i * 4096, sa + (size_t)i * 32768);
#pragma unroll
    for (int g = 0; g < 4; g++)          // B rows g*32 + rA (gate-major)
        CP_ASYNC16(st + A_BYTES + dA + g * 4096, sw + (size_t)g * 1048576);
}

// ---------------- GEMM + fused LSTM kernel ----------------
__global__ void __launch_bounds__(THREADS, 2)
lstm_mma4_kernel(const float* __restrict__ bi, const float* __restrict__ bfv,
                 const float* __restrict__ bo, const float* __restrict__ bc,
                 const float* __restrict__ c,
                 float* __restrict__ out_h, float* __restrict__ out_c) {
    extern __shared__ char smem[];
    float* smf = (float*)smem;
    const uint32_t sb = smem_u32(smem);

    const int tid  = threadIdx.x;
    const int wid  = tid >> 5;
    const int lane = tid & 31;
    const int warp_m = wid >> 2;      // 0..1 (64 rows each)
    const int warp_n = wid & 3;       // 0..3 (= gate, 32 cols each)
    const int j0 = blockIdx.x * JBLK;
    const int m0 = blockIdx.y * TILE_M;

    // bias -> smem [g*32 + jj]
    if (tid < 128) {
        const int g = tid >> 5, jj = tid & 31;
        const float* bp = (g == 0) ? bi : (g == 1) ? bfv : (g == 2) ? bo : bc;
        smf[tid] = bp[j0 + jj];
    }

    // -------- producer addressing (cp.async) --------
    const int rA  = tid >> 3;                 // 0..31
    const int seg = tid & 7;                  // 16B granule within 128B row
    const uint32_t dA = (uint32_t)(rA * 128 + ((seg ^ (rA & 7)) << 4));
    const __half* gsA0 = g_scrh + SCR_X + (size_t)(m0 + rA) * DH + seg * 8;
    const __half* gsA1 = g_scrh + SCR_H + (size_t)(m0 + rA) * DH + seg * 8;
    const __half* gsB  = g_scrh + SCR_W + (size_t)(j0 + rA) * DH + seg * 8;

    // -------- consumer (ldmatrix) addressing --------
    const uint32_t l7x = (uint32_t)((lane & 7) << 4);   // swizzle XOR term
    const uint32_t aoffb = (uint32_t)((warp_m * 64 + (lane & 15)) * 128);
    const uint32_t koffA = (uint32_t)((lane >> 4) << 4);
    const uint32_t boffb = (uint32_t)(A_BYTES +
                          (warp_n * 32 + (lane & 7) + (((lane >> 4) & 1) << 3)) * 128);
    const uint32_t koffB = (uint32_t)(((lane >> 3) & 1) << 4);

    float acc[4][4][4];
#pragma unroll
    for (int mi = 0; mi < 4; mi++)
#pragma unroll
        for (int ni = 0; ni < 4; ni++)
#pragma unroll
            for (int r = 0; r < 4; r++) acc[mi][ni][r] = 0.0f;

    // -------- prologue: stages 0,1 --------
    issue_stage(sb + SM_STAGE_B + 0 * STAGE_BYTES, 0, dA, gsA0, gsA1, gsB);
    CP_COMMIT();
    issue_stage(sb + SM_STAGE_B + 1 * STAGE_BYTES, 1, dA, gsA0, gsA1, gsB);
    CP_COMMIT();

    // -------- main loop --------
    int s = 0;   // compute buffer
    int u = 2;   // fill buffer
#pragma unroll 1
    for (int t = 0; t < NCHUNK; t++) {
        CP_WAIT(1);
        __syncthreads();
        if (t + 2 < NCHUNK) {
            issue_stage(sb + SM_STAGE_B + u * STAGE_BYTES, t + 2, dA, gsA0, gsA1, gsB);
        } else if (t == NCHUNK - 1) {
            // drain: prefetch the c tile (128 x 32 f32 = 16KB) into free smem.
            // Stage 2 was last computed on at t=29; all warps are past that sync.
#pragma unroll
            for (int i = 0; i < 4; i++) {
                const int q = tid + i * THREADS;          // 0..1023 16B chunks
                const int row = q >> 3, c4 = q & 7;
                CP_ASYNC16(sb + SM_C_BYTES + q * 16,
                           c + (size_t)(m0 + row) * DH + j0 + c4 * 4);
            }
        }
        CP_COMMIT();

        const uint32_t st = sb + SM_STAGE_B + s * STAGE_BYTES;
#pragma unroll
        for (int ks = 0; ks < 4; ks++) {          // 4 x k16 per 64-wide chunk
            const uint32_t tA = (uint32_t)(ks * 32 + koffA) ^ l7x;
            const uint32_t tB = (uint32_t)(ks * 32 + koffB) ^ l7x;
            uint32_t b0[4], b1[4];
            LDSM4(b0, st + boffb + tB);           // ni 0,1 (n0-15)
            LDSM4(b1, st + boffb + 2048 + tB);    // ni 2,3 (n16-31)
#pragma unroll
            for (int mi = 0; mi < 4; mi++) {
                uint32_t a[4];
                LDSM4(a, st + aoffb + mi * 2048 + tA);
                mma_f16(acc[mi][0], a, b0 + 0);
                mma_f16(acc[mi][1], a, b0 + 2);
                mma_f16(acc[mi][2], a, b1 + 0);
                mma_f16(acc[mi][3], a, b1 + 2);
            }
        }
        s = (s == 2) ? 0 : s + 1;
        u = (u == 2) ? 0 : u + 1;
    }
    CP_WAIT(0);
    __syncthreads();   // stages dead; dump may alias them; c tile landed

    // -------- dump accumulators to smem --------
    {
        float* dump = smf + 128;    // byte 512
        const int q  = lane >> 2;
        const int tg = lane & 3;
        const int dr = warp_m * 64 + q;
        const int dc = warp_n * 32 + tg * 2;
#pragma unroll
        for (int mi = 0; mi < 4; mi++)
#pragma unroll
            for (int ni = 0; ni < 4; ni++) {
                float2 v0 = { acc[mi][ni][0], acc[mi][ni][1] };
                float2 v1 = { acc[mi][ni][2], acc[mi][ni][3] };
                *(float2*)(dump + (dr + mi * 16) * DUMP_PITCH + dc + ni * 8) = v0;
                *(float2*)(dump + (dr + mi * 16 + 8) * DUMP_PITCH + dc + ni * 8) = v1;
            }
    }
    __syncthreads();

    // -------- fused LSTM epilogue --------
    {
        const float* dump = smf + 128;
        const float* bias = smf;
        const float* csm  = smf + SM_C_BYTES / 4;   // c tile, pitch 32 floats
        const int row8 = tid >> 3;
        const int jg = (tid & 7) * 4;
        const float4 bi4 = *(const float4*)(bias + jg);
        const float4 bf4 = *(const float4*)(bias + 32 + jg);
        const float4 bo4 = *(const float4*)(bias + 64 + jg);
        const float4 bc4 = *(const float4*)(bias + 96 + jg);
#pragma unroll
        for (int p = 0; p < 4; p++) {
            const int row = row8 + p * 32;
            const float4 gi = *(const float4*)(dump + row * DUMP_PITCH + jg);
            const float4 gf = *(const float4*)(dump + row * DUMP_PITCH + 32 + jg);
            const float4 go = *(const float4*)(dump + row * DUMP_PITCH + 64 + jg);
            const float4 gc = *(const float4*)(dump + row * DUMP_PITCH + 96 + jg);
            const float4 ci = *(const float4*)(csm + row * 32 + jg);
            const size_t o = (size_t)(m0 + row) * DH + j0 + jg;
            float4 nh, nc;
            {
                float ig = fast_sigmoid(gi.x + bi4.x), fg = fast_sigmoid(gf.x + bf4.x);
                float og = fast_sigmoid(go.x + bo4.x), cg = fast_tanh(gc.x + bc4.x);
                nc.x = fg * ci.x + ig * cg;  nh.x = og * fast_tanh(nc.x);
            }
            {
                float ig = fast_sigmoid(gi.y + bi4.y), fg = fast_sigmoid(gf.y + bf4.y);
                float og = fast_sigmoid(go.y + bo4.y), cg = fast_tanh(gc.y + bc4.y);
                nc.y = fg * ci.y + ig * cg;  nh.y = og * fast_tanh(nc.y);
            }
            {
                float ig = fast_sigmoid(gi.z + bi4.z), fg = fast_sigmoid(gf.z + bf4.z);
                float og = fast_sigmoid(go.z + bo4.z), cg = fast_tanh(gc.z + bc4.z);
                nc.z = fg * ci.z + ig * cg;  nh.z = og * fast_tanh(nc.z);
            }
            {
                float ig = fast_sigmoid(gi.w + bi4.w), fg = fast_sigmoid(gf.w + bf4.w);
                float og = fast_sigmoid(go.w + bo4.w), cg = fast_tanh(gc.w + bc4.w);
                nc.w = fg * ci.w + ig * cg;  nh.w = og * fast_tanh(nc.w);
            }
            *(float4*)(out_h + o) = nh;
            *(float4*)(out_c + o) = nc;
        }
    }
}

// ---------------- Host launch ----------------
extern "C" void kernel_launch(void* const* d_in, const int* in_sizes, int n_in,
                              void* d_out, int out_size) {
    const float* x  = (const float*)d_in[0];
    const float* h  = (const float*)d_in[1];
    const float* c  = (const float*)d_in[2];
    const float* Wi = (const float*)d_in[3];
    const float* bi = (const float*)d_in[4];
    const float* Ui = (const float*)d_in[5];
    const float* Wf = (const float*)d_in[6];
    const float* bf = (const float*)d_in[7];
    const float* Uf = (const float*)d_in[8];
    const float* Wo = (const float*)d_in[9];
    const float* bo = (const float*)d_in[10];
    const float* Uo = (const float*)d_in[11];
    const float* Wc = (const float*)d_in[12];
    const float* bc = (const float*)d_in[13];
    const float* Uc = (const float*)d_in[14];
    float* out_h = (float*)d_out;
    float* out_c = out_h + (size_t)BATCH * DH;

    static bool once = false;
    if (!once) {
        cudaFuncSetAttribute(lstm_mma4_kernel, cudaFuncAttributeMaxDynamicSharedMemorySize,
                             SMEM_TOTAL);
        once = true;
    }

    // 1) round all inputs to fp16 into scratch (single launch)
    round_all_kernel<<<24576, THREADS>>>(x, h, Wi, Wf, Wo, Wc, Ui, Uf, Uo, Uc);

    // 2) GEMM + fused gates
    dim3 grid(DH / JBLK, BATCH / TILE_M);   // (32, 64)
    lstm_mma4_kernel<<<grid, THREADS, SMEM_TOTAL>>>(bi, bf, bo, bc, c, out_h, out_c);
}

// round 8
// speedup vs baseline: 3.3010x; 1.0132x over previous
#include <cuda_runtime.h>
#include <cuda_fp16.h>
#include <cstdint>

// ---------------- Problem constants ----------------
#define BATCH   8192
#define DH      1024
#define TILE_M  128             // batch rows per CTA
#define JBLK    32              // hidden cols per CTA (per gate)
#define KCH     64              // K elems per chunk (fp16: 128B rows)
#define NCHUNK  32              // 2*1024/64
#define THREADS 256

// ---------------- fp16 scratch (pre-rounded inputs), offsets in halfs ----------------
#define SCR_X 0u
#define SCR_H 8388608u
#define SCR_W 16777216u          // 8 matrices of 1048576 halfs: Wi,Wf,Wo,Wc,Ui,Uf,Uo,Uc
__device__ __half g_scrh[25165824];   // ~50.3 MB static scratch

// ---------------- SMEM layout ----------------
// [0,512)  bias (4 gates x 32 floats); [512,..) 3 stages x (A 16KB + B 16KB)
// epilogue: dump 128x132 floats at byte 512 (aliases stages 0/1 + 2KB of stage 2);
//           c tile 16KB at byte 70144 (inside stage 2, clear of the dump)
#define SM_STAGE_B  512
#define A_BYTES     16384
#define STAGE_BYTES 32768
#define DUMP_PITCH  132
#define SM_C_BYTES  70144
#define SMEM_TOTAL  (512 + 3 * STAGE_BYTES)   // 98816 -> 2 CTAs/SM

// ---------------- helpers ----------------
__device__ __forceinline__ uint32_t smem_u32(const void* p) {
    uint32_t a;
    asm("{ .reg .u64 t; cvta.to.shared.u64 t, %1; cvt.u32.u64 %0, t; }" : "=r"(a) : "l"(p));
    return a;
}
__device__ __forceinline__ void mma_f16(float* d, const uint32_t* a, const uint32_t* b) {
    asm volatile(
        "mma.sync.aligned.m16n8k16.row.col.f32.f16.f16.f32 "
        "{%0,%1,%2,%3}, {%4,%5,%6,%7}, {%8,%9}, {%0,%1,%2,%3};"
        : "+f"(d[0]), "+f"(d[1]), "+f"(d[2]), "+f"(d[3])
        : "r"(a[0]), "r"(a[1]), "r"(a[2]), "r"(a[3]), "r"(b[0]), "r"(b[1]));
}
#define LDSM4(r, addr)                                                            \
    asm volatile("ldmatrix.sync.aligned.m8n8.x4.shared.b16 {%0,%1,%2,%3}, [%4];"  \
        : "=r"((r)[0]), "=r"((r)[1]), "=r"((r)[2]), "=r"((r)[3]) : "r"(addr))
#define CP_ASYNC16(dst, src) \
    asm volatile("cp.async.cg.shared.global [%0], [%1], 16;" :: "r"(dst), "l"(src))
#define CP_COMMIT()  asm volatile("cp.async.commit_group;" ::: "memory")
#define CP_WAIT(n)   asm volatile("cp.async.wait_group %0;" :: "n"(n) : "memory")

__device__ __forceinline__ float fast_sigmoid(float v) { return 1.0f / (1.0f + __expf(-v)); }
__device__ __forceinline__ float fast_tanh(float v) {
    return 1.0f - 2.0f / (__expf(2.0f * v) + 1.0f);   // exact +/-1 at large |v|
}

// ---------------- merged rounding pass (fp32 -> fp16 RN), one launch ----------------
// 24 regions of 1M floats, 512 blocks/region, 8 floats/thread, 16B stores.
__global__ void __launch_bounds__(THREADS)
round_all_kernel(const float* __restrict__ x, const float* __restrict__ h,
                 const float* __restrict__ p0, const float* __restrict__ p1,
                 const float* __restrict__ p2, const float* __restrict__ p3,
                 const float* __restrict__ p4, const float* __restrict__ p5,
                 const float* __restrict__ p6, const float* __restrict__ p7) {
    const int r  = blockIdx.x >> 9;
    const int bi = blockIdx.x & 511;
    const size_t off = ((size_t)bi * THREADS + threadIdx.x) * 8;
    const float* src;
    size_t dst;
    if (r < 8) {
        src = x + (((size_t)r) << 20) + off;
        dst = SCR_X + (((size_t)r) << 20) + off;
    } else if (r < 16) {
        src = h + (((size_t)(r - 8)) << 20) + off;
        dst = SCR_H + (((size_t)(r - 8)) << 20) + off;
    } else {
        const int g = r - 16;
        const float* wp = (g == 0) ? p0 : (g == 1) ? p1 : (g == 2) ? p2 : (g == 3) ? p3
                         : (g == 4) ? p4 : (g == 5) ? p5 : (g == 6) ? p6 : p7;
        src = wp + off;
        dst = SCR_W + (((size_t)g) << 20) + off;
    }
    float4 v0 = *(const float4*)src;
    float4 v1 = *(const float4*)(src + 4);
    __half2 a0 = __floats2half2_rn(v0.x, v0.y), a1 = __floats2half2_rn(v0.z, v0.w);
    __half2 a2 = __floats2half2_rn(v1.x, v1.y), a3 = __floats2half2_rn(v1.z, v1.w);
    uint4 w = { *(uint32_t*)&a0, *(uint32_t*)&a1, *(uint32_t*)&a2, *(uint32_t*)&a3 };
    *(uint4*)(g_scrh + dst) = w;
}

// ---------------- stage producer ----------------
__device__ __forceinline__ void issue_stage(uint32_t st, int tt, uint32_t dA,
                                            const __half* gsA0, const __half* gsA1,
                                            const __half* gsB) {
    const int p = tt >> 4;               // 0: x/W, 1: h/U
    const int k = (tt & 15) * KCH;
    const __half* sa = (p ? gsA1 : gsA0) + k;
    const __half* sw = gsB + (size_t)p * 4194304 + k;
#pragma unroll
    for (int i = 0; i < 4; i++)          // A rows rA + 32*i (row stride 1024 halfs)
        CP_ASYNC16(st + dA + i * 4096, sa + (size_t)i * 32768);
#pragma unroll
    for (int g = 0; g < 4; g++)          // B rows g*32 + rA (gate-major)
        CP_ASYNC16(st + A_BYTES + dA + g * 4096, sw + (size_t)g * 1048576);
}

// ---------------- GEMM + fused LSTM kernel ----------------
__global__ void __launch_bounds__(THREADS, 2)
lstm_mma5_kernel(const float* __restrict__ bi, const float* __restrict__ bfv,
                 const float* __restrict__ bo, const float* __restrict__ bc,
                 const float* __restrict__ c,
                 float* __restrict__ out_h, float* __restrict__ out_c) {
    extern __shared__ char smem[];
    float* smf = (float*)smem;
    const uint32_t sb = smem_u32(smem);

    const int tid  = threadIdx.x;
    const int wid  = tid >> 5;
    const int lane = tid & 31;
    const int warp_m = wid >> 2;      // 0..1 (64 rows each)
    const int warp_n = wid & 3;       // 0..3 (= gate, 32 cols each)
    const int j0 = blockIdx.x * JBLK;
    const int m0 = blockIdx.y * TILE_M;

    // bias -> smem [g*32 + jj]
    if (tid < 128) {
        const int g = tid >> 5, jj = tid & 31;
        const float* bp = (g == 0) ? bi : (g == 1) ? bfv : (g == 2) ? bo : bc;
        smf[tid] = bp[j0 + jj];
    }

    // -------- producer addressing (cp.async) --------
    const int rA  = tid >> 3;                 // 0..31
    const int seg = tid & 7;                  // 16B granule within 128B row
    const uint32_t dA = (uint32_t)(rA * 128 + ((seg ^ (rA & 7)) << 4));
    const __half* gsA0 = g_scrh + SCR_X + (size_t)(m0 + rA) * DH + seg * 8;
    const __half* gsA1 = g_scrh + SCR_H + (size_t)(m0 + rA) * DH + seg * 8;
    const __half* gsB  = g_scrh + SCR_W + (size_t)(j0 + rA) * DH + seg * 8;

    // -------- consumer (ldmatrix) addressing --------
    const uint32_t l7x = (uint32_t)((lane & 7) << 4);   // swizzle XOR term
    const uint32_t aoffb = (uint32_t)((warp_m * 64 + (lane & 15)) * 128);
    const uint32_t koffA = (uint32_t)((lane >> 4) << 4);
    const uint32_t boffb = (uint32_t)(A_BYTES +
                          (warp_n * 32 + (lane & 7) + (((lane >> 4) & 1) << 3)) * 128);
    const uint32_t koffB = (uint32_t)(((lane >> 3) & 1) << 4);

    float acc[4][4][4];
#pragma unroll
    for (int mi = 0; mi < 4; mi++)
#pragma unroll
        for (int ni = 0; ni < 4; ni++)
#pragma unroll
            for (int r = 0; r < 4; r++) acc[mi][ni][r] = 0.0f;

    // -------- prologue: stages 0,1 --------
    issue_stage(sb + SM_STAGE_B + 0 * STAGE_BYTES, 0, dA, gsA0, gsA1, gsB);
    CP_COMMIT();
    issue_stage(sb + SM_STAGE_B + 1 * STAGE_BYTES, 1, dA, gsA0, gsA1, gsB);
    CP_COMMIT();

    // -------- main loop --------
    int s = 0;   // compute buffer
    int u = 2;   // fill buffer
#pragma unroll 1
    for (int t = 0; t < NCHUNK; t++) {
        CP_WAIT(1);
        __syncthreads();
        if (t + 2 < NCHUNK) {
            issue_stage(sb + SM_STAGE_B + u * STAGE_BYTES, t + 2, dA, gsA0, gsA1, gsB);
        } else if (t == NCHUNK - 1) {
            // drain: prefetch the c tile (128 x 32 f32 = 16KB) into free smem.
#pragma unroll
            for (int i = 0; i < 4; i++) {
                const int q = tid + i * THREADS;          // 0..1023 16B chunks
                const int row = q >> 3, c4 = q & 7;
                CP_ASYNC16(sb + SM_C_BYTES + q * 16,
                           c + (size_t)(m0 + row) * DH + j0 + c4 * 4);
            }
        }
        CP_COMMIT();

        const uint32_t st = sb + SM_STAGE_B + s * STAGE_BYTES;
        // warp-skewed k-subtile order: spreads the post-barrier LDSM burst of the
        // 16 warps/SM across 4 phases instead of colliding on the smem crossbar.
#pragma unroll
        for (int ks = 0; ks < 4; ks++) {
            const uint32_t kk = (uint32_t)((ks + wid) & 3);
            const uint32_t tA = (kk * 32 + koffA) ^ l7x;
            const uint32_t tB = (kk * 32 + koffB) ^ l7x;
            uint32_t b0[4], b1[4];
            LDSM4(b0, st + boffb + tB);           // ni 0,1 (n0-15)
            LDSM4(b1, st + boffb + 2048 + tB);    // ni 2,3 (n16-31)
#pragma unroll
            for (int mi = 0; mi < 4; mi++) {
                uint32_t a[4];
                LDSM4(a, st + aoffb + mi * 2048 + tA);
                mma_f16(acc[mi][0], a, b0 + 0);
                mma_f16(acc[mi][1], a, b0 + 2);
                mma_f16(acc[mi][2], a, b1 + 0);
                mma_f16(acc[mi][3], a, b1 + 2);
            }
        }
        s = (s == 2) ? 0 : s + 1;
        u = (u == 2) ? 0 : u + 1;
    }
    CP_WAIT(0);
    __syncthreads();   // stages dead; dump may alias them; c tile landed

    // -------- dump accumulators to smem --------
    {
        float* dump = smf + 128;    // byte 512
        const int q  = lane >> 2;
        const int tg = lane & 3;
        const int dr = warp_m * 64 + q;
        const int dc = warp_n * 32 + tg * 2;
#pragma unroll
        for (int mi = 0; mi < 4; mi++)
#pragma unroll
            for (int ni = 0; ni < 4; ni++) {
                float2 v0 = { acc[mi][ni][0], acc[mi][ni][1] };
                float2 v1 = { acc[mi][ni][2], acc[mi][ni][3] };
                *(float2*)(dump + (dr + mi * 16) * DUMP_PITCH + dc + ni * 8) = v0;
                *(float2*)(dump + (dr + mi * 16 + 8) * DUMP_PITCH + dc + ni * 8) = v1;
            }
    }
    __syncthreads();

    // -------- fused LSTM epilogue --------
    {
        const float* dump = smf + 128;
        const float* bias = smf;
        const float* csm  = smf + SM_C_BYTES / 4;   // c tile, pitch 32 floats
        const int row8 = tid >> 3;
        const int jg = (tid & 7) * 4;
        const float4 bi4 = *(const float4*)(bias + jg);
        const float4 bf4 = *(const float4*)(bias + 32 + jg);
        const float4 bo4 = *(const float4*)(bias + 64 + jg);
        const float4 bc4 = *(const float4*)(bias + 96 + jg);
#pragma unroll
        for (int p = 0; p < 4; p++) {
            const int row = row8 + p * 32;
            const float4 gi = *(const float4*)(dump + row * DUMP_PITCH + jg);
            const float4 gf = *(const float4*)(dump + row * DUMP_PITCH + 32 + jg);
            const float4 go = *(const float4*)(dump + row * DUMP_PITCH + 64 + jg);
            const float4 gc = *(const float4*)(dump + row * DUMP_PITCH + 96 + jg);
            const float4 ci = *(const float4*)(csm + row * 32 + jg);
            const size_t o = (size_t)(m0 + row) * DH + j0 + jg;
            float4 nh, nc;
            {
                float ig = fast_sigmoid(gi.x + bi4.x), fg = fast_sigmoid(gf.x + bf4.x);
                float og = fast_sigmoid(go.x + bo4.x), cg = fast_tanh(gc.x + bc4.x);
                nc.x = fg * ci.x + ig * cg;  nh.x = og * fast_tanh(nc.x);
            }
            {
                float ig = fast_sigmoid(gi.y + bi4.y), fg = fast_sigmoid(gf.y + bf4.y);
                float og = fast_sigmoid(go.y + bo4.y), cg = fast_tanh(gc.y + bc4.y);
                nc.y = fg * ci.y + ig * cg;  nh.y = og * fast_tanh(nc.y);
            }
            {
                float ig = fast_sigmoid(gi.z + bi4.z), fg = fast_sigmoid(gf.z + bf4.z);
                float og = fast_sigmoid(go.z + bo4.z), cg = fast_tanh(gc.z + bc4.z);
                nc.z = fg * ci.z + ig * cg;  nh.z = og * fast_tanh(nc.z);
            }
            {
                float ig = fast_sigmoid(gi.w + bi4.w), fg = fast_sigmoid(gf.w + bf4.w);
                float og = fast_sigmoid(go.w + bo4.w), cg = fast_tanh(gc.w + bc4.w);
                nc.w = fg * ci.w + ig * cg;  nh.w = og * fast_tanh(nc.w);
            }
            *(float4*)(out_h + o) = nh;
            *(float4*)(out_c + o) = nc;
        }
    }
}

// ---------------- Host launch ----------------
extern "C" void kernel_launch(void* const* d_in, const int* in_sizes, int n_in,
                              void* d_out, int out_size) {
    const float* x  = (const float*)d_in[0];
    const float* h  = (const float*)d_in[1];
    const float* c  = (const float*)d_in[2];
    const float* Wi = (const float*)d_in[3];
    const float* bi = (const float*)d_in[4];
    const float* Ui = (const float*)d_in[5];
    const float* Wf = (const float*)d_in[6];
    const float* bf = (const float*)d_in[7];
    const float* Uf = (const float*)d_in[8];
    const float* Wo = (const float*)d_in[9];
    const float* bo = (const float*)d_in[10];
    const float* Uo = (const float*)d_in[11];
    const float* Wc = (const float*)d_in[12];
    const float* bc = (const float*)d_in[13];
    const float* Uc = (const float*)d_in[14];
    float* out_h = (float*)d_out;
    float* out_c = out_h + (size_t)BATCH * DH;

    static bool once = false;
    if (!once) {
        cudaFuncSetAttribute(lstm_mma5_kernel, cudaFuncAttributeMaxDynamicSharedMemorySize,
                             SMEM_TOTAL);
        once = true;
    }

    // 1) round all inputs to fp16 into scratch (single launch)
    round_all_kernel<<<12288, THREADS>>>(x, h, Wi, Wf, Wo, Wc, Ui, Uf, Uo, Uc);

    // 2) GEMM + fused gates
    dim3 grid(DH / JBLK, BATCH / TILE_M);   // (32, 64)
    lstm_mma5_kernel<<<grid, THREADS, SMEM_TOTAL>>>(bi, bf, bo, bc, c, out_h, out_c);
}